// round 7
// baseline (speedup 1.0000x reference)
#include <cuda_runtime.h>
#include <cuda_bf16.h>
#include <cstdint>

// Problem constants
#define BATCH 2
#define SEQ   2048
#define EMB   1024
#define NH    16
#define HD    64
#define FF    4096
#define NL    4
#define VOC   32000
#define BS    (BATCH*SEQ)   // 4096 rows

// ---------------- scratch (device globals; no allocation) ----------------
__device__ float g_h   [(size_t)BS * EMB];        // hidden state
__device__ float g_qkv [(size_t)BS * 3 * EMB];    // qkv projections
__device__ float g_attn[(size_t)BS * EMB];        // attention output
__device__ float g_tmp [(size_t)BS * EMB];        // pre-LN buffer
__device__ float g_ff  [(size_t)BS * FF];         // FF hidden

// ---------------- embed: h = word_embed[x] + pos_embed ----------------
// NOTE: tokens are int32 (JAX x64 is disabled; "int64" in the reference is
// silently int32 at runtime).
__global__ void __launch_bounds__(256) embed_kernel(
    const int* __restrict__ x, const float* __restrict__ we,
    const float* __restrict__ pe, float* __restrict__ h)
{
    int row = blockIdx.x;              // 0..BS-1
    int s   = row % SEQ;
    int tok = x[row];
    int c = threadIdx.x * 4;           // 256 threads * 4 = 1024
    float4 a = *(const float4*)(we + (size_t)tok * EMB + c);
    float4 b = *(const float4*)(pe + (size_t)s   * EMB + c);
    float4 o; o.x = a.x + b.x; o.y = a.y + b.y; o.z = a.z + b.z; o.w = a.w + b.w;
    *(float4*)(h + (size_t)row * EMB + c) = o;
}

// ---------------- tiled SGEMM: C = A(MxK) @ B + [bias] [relu] ----------------
// NN: B is row-major (K x N).  NT: B is row-major (N x K), compute A @ B^T.
// Requirements (all satisfied by this problem): M%128==0, N%128==0, K%8==0.
#define TBM 128
#define TBN 128
#define TBK 8

template<bool TRANSB, bool BIAS, bool RELU>
__global__ void __launch_bounds__(256) sgemm_kernel(
    const float* __restrict__ A, const float* __restrict__ B,
    const float* __restrict__ bias, float* __restrict__ C,
    int M, int N, int K)
{
    __shared__ float As[TBK][TBM];
    __shared__ float Bs[TBK][TBN + 4];

    const int tid = threadIdx.x;
    const int bx = blockIdx.x, by = blockIdx.y;
    const int tx = tid & 15, ty = tid >> 4;

    const float* Ablk = A + (size_t)by * TBM * K;

    float acc[8][8];
#pragma unroll
    for (int i = 0; i < 8; i++)
#pragma unroll
        for (int j = 0; j < 8; j++) acc[i][j] = 0.f;

    const int a_r = tid >> 1;          // 0..127
    const int a_c = (tid & 1) * 4;     // 0 or 4
    const int bn_r = tid >> 5;         // 0..7
    const int bn_c = (tid & 31) * 4;   // 0..124
    const int bt_n = tid >> 1;         // 0..127
    const int bt_k = (tid & 1) * 4;    // 0 or 4

    for (int k0 = 0; k0 < K; k0 += TBK) {
        float4 av = *(const float4*)(Ablk + (size_t)a_r * K + k0 + a_c);
        As[a_c + 0][a_r] = av.x; As[a_c + 1][a_r] = av.y;
        As[a_c + 2][a_r] = av.z; As[a_c + 3][a_r] = av.w;
        if (!TRANSB) {
            float4 bv = *(const float4*)(B + (size_t)(k0 + bn_r) * N + (size_t)bx * TBN + bn_c);
            *(float4*)&Bs[bn_r][bn_c] = bv;
        } else {
            float4 bv = *(const float4*)(B + (size_t)((size_t)bx * TBN + bt_n) * K + k0 + bt_k);
            Bs[bt_k + 0][bt_n] = bv.x; Bs[bt_k + 1][bt_n] = bv.y;
            Bs[bt_k + 2][bt_n] = bv.z; Bs[bt_k + 3][bt_n] = bv.w;
        }
        __syncthreads();
#pragma unroll
        for (int kk = 0; kk < TBK; kk++) {
            float4 a0 = *(const float4*)&As[kk][ty * 4];
            float4 a1 = *(const float4*)&As[kk][64 + ty * 4];
            float4 b0 = *(const float4*)&Bs[kk][tx * 4];
            float4 b1 = *(const float4*)&Bs[kk][64 + tx * 4];
            float a[8] = {a0.x, a0.y, a0.z, a0.w, a1.x, a1.y, a1.z, a1.w};
            float b[8] = {b0.x, b0.y, b0.z, b0.w, b1.x, b1.y, b1.z, b1.w};
#pragma unroll
            for (int i = 0; i < 8; i++)
#pragma unroll
                for (int j = 0; j < 8; j++) acc[i][j] = fmaf(a[i], b[j], acc[i][j]);
        }
        __syncthreads();
    }

#pragma unroll
    for (int ih = 0; ih < 2; ih++)
#pragma unroll
        for (int u = 0; u < 4; u++) {
            int row = by * TBM + ih * 64 + ty * 4 + u;
#pragma unroll
            for (int jh = 0; jh < 2; jh++) {
                int col = bx * TBN + jh * 64 + tx * 4;
                float4 v;
                v.x = acc[ih * 4 + u][jh * 4 + 0];
                v.y = acc[ih * 4 + u][jh * 4 + 1];
                v.z = acc[ih * 4 + u][jh * 4 + 2];
                v.w = acc[ih * 4 + u][jh * 4 + 3];
                if (BIAS) {
                    float4 bb = *(const float4*)(bias + col);
                    v.x += bb.x; v.y += bb.y; v.z += bb.z; v.w += bb.w;
                }
                if (RELU) {
                    v.x = fmaxf(v.x, 0.f); v.y = fmaxf(v.y, 0.f);
                    v.z = fmaxf(v.z, 0.f); v.w = fmaxf(v.w, 0.f);
                }
                *(float4*)(C + (size_t)row * N + col) = v;
            }
        }
}

// ---------------- fused attention: one block per (b, h, query) ----------------
// qkv layout: qkv[(b*SEQ+s)*3E + h*192 + t*64 + d], t: 0=K, 1=Q, 2=V
__global__ void __launch_bounds__(256) attn_kernel(
    const float* __restrict__ qkv, float* __restrict__ out)
{
    const int qi = blockIdx.x, h = blockIdx.y, b = blockIdx.z;
    const int tid = threadIdx.x;
    __shared__ float q_sh[HD];
    __shared__ float sc[SEQ];
    __shared__ float red[8];
    __shared__ float stats[2];
    __shared__ float outp[4][HD];

    const float* base = qkv + (size_t)b * SEQ * (3 * EMB);
    if (tid < HD)
        q_sh[tid] = base[(size_t)qi * (3 * EMB) + h * (3 * HD) + HD + tid];
    __syncthreads();

    // scores (causal: k <= qi)
    float lmax = -1e30f;
    for (int k = tid; k <= qi; k += 256) {
        const float* kp = base + (size_t)k * (3 * EMB) + h * (3 * HD);
        float d = 0.f;
#pragma unroll
        for (int dd = 0; dd < HD; dd++) d = fmaf(q_sh[dd], kp[dd], d);
        d *= 0.125f;                // 1/sqrt(64)
        sc[k] = d;
        lmax = fmaxf(lmax, d);
    }
#pragma unroll
    for (int o = 16; o; o >>= 1) lmax = fmaxf(lmax, __shfl_xor_sync(0xffffffffu, lmax, o));
    if ((tid & 31) == 0) red[tid >> 5] = lmax;
    __syncthreads();
    if (tid == 0) {
        float m = red[0];
#pragma unroll
        for (int i = 1; i < 8; i++) m = fmaxf(m, red[i]);
        stats[0] = m;
    }
    __syncthreads();
    const float m = stats[0];

    float lsum = 0.f;
    for (int k = tid; k <= qi; k += 256) {
        float p = __expf(sc[k] - m);
        sc[k] = p;
        lsum += p;
    }
#pragma unroll
    for (int o = 16; o; o >>= 1) lsum += __shfl_xor_sync(0xffffffffu, lsum, o);
    if ((tid & 31) == 0) red[tid >> 5] = lsum;
    __syncthreads();
    if (tid == 0) {
        float s = 0.f;
#pragma unroll
        for (int i = 0; i < 8; i++) s += red[i];
        stats[1] = 1.f / s;
    }
    __syncthreads();
    const float inv = stats[1];

    // AV: thread -> (chunk c, dim d)
    const int d = tid & 63, c = tid >> 6;
    float acc = 0.f;
    for (int k = c; k <= qi; k += 4)
        acc += sc[k] * base[(size_t)k * (3 * EMB) + h * (3 * HD) + 2 * HD + d];
    outp[c][d] = acc;
    __syncthreads();
    if (tid < HD) {
        float v = (outp[0][tid] + outp[1][tid] + outp[2][tid] + outp[3][tid]) * inv;
        out[(size_t)(b * SEQ + qi) * EMB + h * HD + tid] = v;
    }
}

// ---------------- fused LayerNorm + residual: h += LN(x)*g + b ----------------
__global__ void __launch_bounds__(256) ln_add_kernel(
    const float* __restrict__ x, const float* __restrict__ gam,
    const float* __restrict__ bet, float* __restrict__ h)
{
    const int row = blockIdx.x;
    const int tid = threadIdx.x;
    __shared__ float red[8];
    __shared__ float stats[2];

    const float* xr = x + (size_t)row * EMB;
    const int c = tid * 4;
    float4 v = *(const float4*)(xr + c);
    float s = v.x + v.y + v.z + v.w;
#pragma unroll
    for (int o = 16; o; o >>= 1) s += __shfl_xor_sync(0xffffffffu, s, o);
    if ((tid & 31) == 0) red[tid >> 5] = s;
    __syncthreads();
    if (tid == 0) {
        float t = 0.f;
#pragma unroll
        for (int i = 0; i < 8; i++) t += red[i];
        stats[0] = t * (1.f / EMB);
    }
    __syncthreads();
    const float mu = stats[0];

    float dx0 = v.x - mu, dx1 = v.y - mu, dx2 = v.z - mu, dx3 = v.w - mu;
    float sq = dx0 * dx0 + dx1 * dx1 + dx2 * dx2 + dx3 * dx3;
#pragma unroll
    for (int o = 16; o; o >>= 1) sq += __shfl_xor_sync(0xffffffffu, sq, o);
    if ((tid & 31) == 0) red[tid >> 5] = sq;
    __syncthreads();
    if (tid == 0) {
        float t = 0.f;
#pragma unroll
        for (int i = 0; i < 8; i++) t += red[i];
        stats[1] = rsqrtf(t * (1.f / EMB) + 1e-6f);
    }
    __syncthreads();
    const float r = stats[1];

    float4 g4 = *(const float4*)(gam + c);
    float4 b4 = *(const float4*)(bet + c);
    float4 hv = *(float4*)(h + (size_t)row * EMB + c);
    hv.x += dx0 * r * g4.x + b4.x;
    hv.y += dx1 * r * g4.y + b4.y;
    hv.z += dx2 * r * g4.z + b4.z;
    hv.w += dx3 * r * g4.w + b4.w;
    *(float4*)(h + (size_t)row * EMB + c) = hv;
}

// ---------------- launch ----------------
static float* sym_addr(const void* sym) {
    void* p = nullptr;
    cudaGetSymbolAddress(&p, sym);
    return (float*)p;
}

extern "C" void kernel_launch(void* const* d_in, const int* in_sizes, int n_in,
                              void* d_out, int out_size)
{
    const int*   x   = (const int*)d_in[0];   // int32 tokens (JAX x64 disabled)
    const float* we  = (const float*)d_in[1];
    const float* pe  = (const float*)d_in[2];
    const float* KQV = (const float*)d_in[3];
    const float* WO  = (const float*)d_in[4];
    const float* Wup = (const float*)d_in[5];
    const float* bup = (const float*)d_in[6];
    const float* Wdn = (const float*)d_in[7];
    const float* bdn = (const float*)d_in[8];
    const float* g1  = (const float*)d_in[9];
    const float* b1  = (const float*)d_in[10];
    const float* g2  = (const float*)d_in[11];
    const float* b2  = (const float*)d_in[12];
    const float* ub  = (const float*)d_in[13];
    float* out = (float*)d_out;

    float* h    = sym_addr(g_h);
    float* qkv  = sym_addr(g_qkv);
    float* attn = sym_addr(g_attn);
    float* tmp  = sym_addr(g_tmp);
    float* ff   = sym_addr(g_ff);

    embed_kernel<<<BS, 256>>>(x, we, pe, h);

    for (int l = 0; l < NL; l++) {
        // qkv = h @ KQV[l]   (4096 x 3072, K=1024)
        sgemm_kernel<false, false, false>
            <<<dim3(3 * EMB / TBN, BS / TBM), 256>>>(
                h, KQV + (size_t)l * EMB * 3 * EMB, nullptr, qkv, BS, 3 * EMB, EMB);

        // attention
        attn_kernel<<<dim3(SEQ, NH, BATCH), 256>>>(qkv, attn);

        // tmp = attn @ WO[l]  (4096 x 1024, K=1024)
        sgemm_kernel<false, false, false>
            <<<dim3(EMB / TBN, BS / TBM), 256>>>(
                attn, WO + (size_t)l * EMB * EMB, nullptr, tmp, BS, EMB, EMB);

        // h += LN(tmp)
        ln_add_kernel<<<BS, 256>>>(tmp, g1 + l * EMB, b1 + l * EMB, h);

        // ff = relu(h @ W_up[l] + b_up[l])  (4096 x 4096, K=1024)
        sgemm_kernel<false, true, true>
            <<<dim3(FF / TBN, BS / TBM), 256>>>(
                h, Wup + (size_t)l * EMB * FF, bup + (size_t)l * FF, ff, BS, FF, EMB);

        // tmp = ff @ W_down[l] + b_down[l]  (4096 x 1024, K=4096)
        sgemm_kernel<false, true, false>
            <<<dim3(EMB / TBN, BS / TBM), 256>>>(
                ff, Wdn + (size_t)l * FF * EMB, bdn + (size_t)l * EMB, tmp, BS, EMB, FF);

        // h += LN(tmp)
        ln_add_kernel<<<BS, 256>>>(tmp, g2 + l * EMB, b2 + l * EMB, h);
    }

    // logits = h @ we^T + unembed_b   (4096 x 32000, K=1024, NT)
    sgemm_kernel<true, true, false>
        <<<dim3(VOC / TBN, BS / TBM), 256>>>(h, we, ub, out, BS, VOC, EMB);
}

// round 9
// speedup vs baseline: 3.3693x; 3.3693x over previous
#include <cuda_runtime.h>
#include <cuda_bf16.h>
#include <cstdint>

// Problem constants
#define BATCH 2
#define SEQ   2048
#define EMB   1024
#define NH    16
#define HD    64
#define FF    4096
#define NL    4
#define VOC   32000
#define BS    (BATCH*SEQ)   // 4096 rows

// ---------------- scratch (device globals; no allocation) ----------------
__device__ float g_h   [(size_t)BS * EMB];
__device__ float g_qkv [(size_t)BS * 3 * EMB];
__device__ float g_attn[(size_t)BS * EMB];
__device__ float g_tmp [(size_t)BS * EMB];
__device__ float g_ff  [(size_t)BS * FF];

// ---------------- embed: h = word_embed[x] + pos_embed ----------------
__global__ void __launch_bounds__(256) embed_kernel(
    const int* __restrict__ x, const float* __restrict__ we,
    const float* __restrict__ pe, float* __restrict__ h)
{
    int row = blockIdx.x;
    int s   = row % SEQ;
    int tok = x[row];
    int c = threadIdx.x * 4;
    float4 a = *(const float4*)(we + (size_t)tok * EMB + c);
    float4 b = *(const float4*)(pe + (size_t)s   * EMB + c);
    float4 o; o.x = a.x + b.x; o.y = a.y + b.y; o.z = a.z + b.z; o.w = a.w + b.w;
    *(float4*)(h + (size_t)row * EMB + c) = o;
}

// ---------------- tiled SGEMM (unchanged from R7) ----------------
#define TBM 128
#define TBN 128
#define TBK 8

template<bool TRANSB, bool BIAS, bool RELU>
__global__ void __launch_bounds__(256) sgemm_kernel(
    const float* __restrict__ A, const float* __restrict__ B,
    const float* __restrict__ bias, float* __restrict__ C,
    int M, int N, int K)
{
    __shared__ float As[TBK][TBM];
    __shared__ float Bs[TBK][TBN + 4];

    const int tid = threadIdx.x;
    const int bx = blockIdx.x, by = blockIdx.y;
    const int tx = tid & 15, ty = tid >> 4;

    const float* Ablk = A + (size_t)by * TBM * K;

    float acc[8][8];
#pragma unroll
    for (int i = 0; i < 8; i++)
#pragma unroll
        for (int j = 0; j < 8; j++) acc[i][j] = 0.f;

    const int a_r = tid >> 1;
    const int a_c = (tid & 1) * 4;
    const int bn_r = tid >> 5;
    const int bn_c = (tid & 31) * 4;
    const int bt_n = tid >> 1;
    const int bt_k = (tid & 1) * 4;

    for (int k0 = 0; k0 < K; k0 += TBK) {
        float4 av = *(const float4*)(Ablk + (size_t)a_r * K + k0 + a_c);
        As[a_c + 0][a_r] = av.x; As[a_c + 1][a_r] = av.y;
        As[a_c + 2][a_r] = av.z; As[a_c + 3][a_r] = av.w;
        if (!TRANSB) {
            float4 bv = *(const float4*)(B + (size_t)(k0 + bn_r) * N + (size_t)bx * TBN + bn_c);
            *(float4*)&Bs[bn_r][bn_c] = bv;
        } else {
            float4 bv = *(const float4*)(B + (size_t)((size_t)bx * TBN + bt_n) * K + k0 + bt_k);
            Bs[bt_k + 0][bt_n] = bv.x; Bs[bt_k + 1][bt_n] = bv.y;
            Bs[bt_k + 2][bt_n] = bv.z; Bs[bt_k + 3][bt_n] = bv.w;
        }
        __syncthreads();
#pragma unroll
        for (int kk = 0; kk < TBK; kk++) {
            float4 a0 = *(const float4*)&As[kk][ty * 4];
            float4 a1 = *(const float4*)&As[kk][64 + ty * 4];
            float4 b0 = *(const float4*)&Bs[kk][tx * 4];
            float4 b1 = *(const float4*)&Bs[kk][64 + tx * 4];
            float a[8] = {a0.x, a0.y, a0.z, a0.w, a1.x, a1.y, a1.z, a1.w};
            float b[8] = {b0.x, b0.y, b0.z, b0.w, b1.x, b1.y, b1.z, b1.w};
#pragma unroll
            for (int i = 0; i < 8; i++)
#pragma unroll
                for (int j = 0; j < 8; j++) acc[i][j] = fmaf(a[i], b[j], acc[i][j]);
        }
        __syncthreads();
    }

#pragma unroll
    for (int ih = 0; ih < 2; ih++)
#pragma unroll
        for (int u = 0; u < 4; u++) {
            int row = by * TBM + ih * 64 + ty * 4 + u;
#pragma unroll
            for (int jh = 0; jh < 2; jh++) {
                int col = bx * TBN + jh * 64 + tx * 4;
                float4 v;
                v.x = acc[ih * 4 + u][jh * 4 + 0];
                v.y = acc[ih * 4 + u][jh * 4 + 1];
                v.z = acc[ih * 4 + u][jh * 4 + 2];
                v.w = acc[ih * 4 + u][jh * 4 + 3];
                if (BIAS) {
                    float4 bb = *(const float4*)(bias + col);
                    v.x += bb.x; v.y += bb.y; v.z += bb.z; v.w += bb.w;
                }
                if (RELU) {
                    v.x = fmaxf(v.x, 0.f); v.y = fmaxf(v.y, 0.f);
                    v.z = fmaxf(v.z, 0.f); v.w = fmaxf(v.w, 0.f);
                }
                *(float4*)(C + (size_t)row * N + col) = v;
            }
        }
}

// ---------------- flash attention: block per (b, h, 64-query tile) ----------------
// qkv layout: qkv[(b*SEQ+s)*3E + h*192 + t*64 + d], t: 0=K, 1=Q, 2=V
// 256 threads. Thread t handles q-row r = t>>2; in S phase it owns k-columns
// k = (t&3) + 4*i (interleaved -> conflict-free Ks reads); in PV phase it owns
// output dims ds = (t&3)*16 .. +15.
#define BQ 64
#define BK 64
#define LDP 68   // padded row stride (floats)

__global__ void __launch_bounds__(256) flash_attn_kernel(
    const float* __restrict__ qkv, float* __restrict__ out)
{
    extern __shared__ float smem[];
    float (*Qs)[LDP] = (float(*)[LDP])smem;
    float (*Ks)[LDP] = (float(*)[LDP])(smem + BQ * LDP);
    float (*Vs)[LDP] = (float(*)[LDP])(smem + 2 * BQ * LDP);
    float (*Ps)[LDP] = (float(*)[LDP])(smem + 3 * BQ * LDP);

    const int qt = blockIdx.x;
    const int h  = blockIdx.y;
    const int b  = blockIdx.z;
    const int tid = threadIdx.x;

    const float* base = qkv + (size_t)b * SEQ * (3 * EMB) + h * (3 * HD);

    // Load Q tile (64x64): 16 threads/row * 16B, 4 passes. Coalesced.
    {
        const int rr = tid >> 4;          // 0..15
        const int cc = (tid & 15) * 4;    // 0..60
#pragma unroll
        for (int p = 0; p < 4; p++) {
            int r = p * 16 + rr;
            *(float4*)&Qs[r][cc] =
                *(const float4*)(base + (size_t)(qt * BQ + r) * (3 * EMB) + HD + cc);
        }
    }
    __syncthreads();

    const int r  = tid >> 2;              // q row within tile
    const int g  = tid & 3;               // group lane (0..3)
    const int ds = g * 16;                // output dim chunk
    const int q_global = qt * BQ + r;

    float m = -1e30f, l = 0.f;
    float o[16];
#pragma unroll
    for (int i = 0; i < 16; i++) o[i] = 0.f;

    const int nkt = qt + 1;               // causal

    for (int kt = 0; kt < nkt; kt++) {
        // Load K and V tiles (coalesced, 256B rows)
        {
            const int rr = tid >> 4;
            const int cc = (tid & 15) * 4;
#pragma unroll
            for (int p = 0; p < 4; p++) {
                int rk = p * 16 + rr;
                const float* src = base + (size_t)(kt * BK + rk) * (3 * EMB);
                *(float4*)&Ks[rk][cc] = *(const float4*)(src + cc);           // K
                *(float4*)&Vs[rk][cc] = *(const float4*)(src + 2 * HD + cc);  // V
            }
        }
        __syncthreads();

        // S phase: 16 interleaved k-columns per thread: k = g + 4*i
        float s[16];
#pragma unroll
        for (int i = 0; i < 16; i++) s[i] = 0.f;
#pragma unroll
        for (int dd = 0; dd < HD; dd += 4) {
            float4 q4 = *(const float4*)&Qs[r][dd];
#pragma unroll
            for (int i = 0; i < 16; i++) {
                float4 k4 = *(const float4*)&Ks[g + 4 * i][dd];
                s[i] = fmaf(q4.x, k4.x, fmaf(q4.y, k4.y,
                       fmaf(q4.z, k4.z, fmaf(q4.w, k4.w, s[i]))));
            }
        }
        const bool diag = (kt == qt);
#pragma unroll
        for (int i = 0; i < 16; i++) {
            s[i] *= 0.125f;                       // 1/sqrt(64)
            if (diag && (kt * BK + g + 4 * i) > q_global) s[i] = -1e30f;
        }

        // online softmax across the 4-thread row group
        float lm = s[0];
#pragma unroll
        for (int i = 1; i < 16; i++) lm = fmaxf(lm, s[i]);
        lm = fmaxf(lm, __shfl_xor_sync(0xffffffffu, lm, 1));
        lm = fmaxf(lm, __shfl_xor_sync(0xffffffffu, lm, 2));
        const float mnew = fmaxf(m, lm);
        const float corr = __expf(m - mnew);
        float psum = 0.f;
#pragma unroll
        for (int i = 0; i < 16; i++) {
            float p = __expf(s[i] - mnew);
            Ps[r][g + 4 * i] = p;
            psum += p;
        }
        psum += __shfl_xor_sync(0xffffffffu, psum, 1);
        psum += __shfl_xor_sync(0xffffffffu, psum, 2);
        l = l * corr + psum;
        m = mnew;
#pragma unroll
        for (int i = 0; i < 16; i++) o[i] *= corr;
        __syncwarp();   // Ps row visible to the 4-thread group (same warp)

        // PV phase: O[r][ds..ds+15] += sum_k Ps[r][k] * Vs[k][ds..]
#pragma unroll 8
        for (int k = 0; k < BK; k++) {
            float p = Ps[r][k];
            float4 v0 = *(const float4*)&Vs[k][ds];
            float4 v1 = *(const float4*)&Vs[k][ds + 4];
            float4 v2 = *(const float4*)&Vs[k][ds + 8];
            float4 v3 = *(const float4*)&Vs[k][ds + 12];
            o[0]  = fmaf(p, v0.x, o[0]);  o[1]  = fmaf(p, v0.y, o[1]);
            o[2]  = fmaf(p, v0.z, o[2]);  o[3]  = fmaf(p, v0.w, o[3]);
            o[4]  = fmaf(p, v1.x, o[4]);  o[5]  = fmaf(p, v1.y, o[5]);
            o[6]  = fmaf(p, v1.z, o[6]);  o[7]  = fmaf(p, v1.w, o[7]);
            o[8]  = fmaf(p, v2.x, o[8]);  o[9]  = fmaf(p, v2.y, o[9]);
            o[10] = fmaf(p, v2.z, o[10]); o[11] = fmaf(p, v2.w, o[11]);
            o[12] = fmaf(p, v3.x, o[12]); o[13] = fmaf(p, v3.y, o[13]);
            o[14] = fmaf(p, v3.z, o[14]); o[15] = fmaf(p, v3.w, o[15]);
        }
        __syncthreads();  // protect Ks/Vs before next tile load
    }

    const float inv = 1.f / l;
    float* op = out + (size_t)(b * SEQ + q_global) * EMB + h * HD + ds;
#pragma unroll
    for (int i = 0; i < 16; i += 4) {
        float4 v = { o[i] * inv, o[i+1] * inv, o[i+2] * inv, o[i+3] * inv };
        *(float4*)(op + i) = v;
    }
}

// ---------------- fused LayerNorm + residual: h += LN(x)*g + b ----------------
__global__ void __launch_bounds__(256) ln_add_kernel(
    const float* __restrict__ x, const float* __restrict__ gam,
    const float* __restrict__ bet, float* __restrict__ h)
{
    const int row = blockIdx.x;
    const int tid = threadIdx.x;
    __shared__ float red[8];
    __shared__ float stats[2];

    const float* xr = x + (size_t)row * EMB;
    const int c = tid * 4;
    float4 v = *(const float4*)(xr + c);
    float s = v.x + v.y + v.z + v.w;
#pragma unroll
    for (int o = 16; o; o >>= 1) s += __shfl_xor_sync(0xffffffffu, s, o);
    if ((tid & 31) == 0) red[tid >> 5] = s;
    __syncthreads();
    if (tid == 0) {
        float t = 0.f;
#pragma unroll
        for (int i = 0; i < 8; i++) t += red[i];
        stats[0] = t * (1.f / EMB);
    }
    __syncthreads();
    const float mu = stats[0];

    float dx0 = v.x - mu, dx1 = v.y - mu, dx2 = v.z - mu, dx3 = v.w - mu;
    float sq = dx0 * dx0 + dx1 * dx1 + dx2 * dx2 + dx3 * dx3;
#pragma unroll
    for (int o = 16; o; o >>= 1) sq += __shfl_xor_sync(0xffffffffu, sq, o);
    if ((tid & 31) == 0) red[tid >> 5] = sq;
    __syncthreads();
    if (tid == 0) {
        float t = 0.f;
#pragma unroll
        for (int i = 0; i < 8; i++) t += red[i];
        stats[1] = rsqrtf(t * (1.f / EMB) + 1e-6f);
    }
    __syncthreads();
    const float r = stats[1];

    float4 g4 = *(const float4*)(gam + c);
    float4 b4 = *(const float4*)(bet + c);
    float4 hv = *(float4*)(h + (size_t)row * EMB + c);
    hv.x += dx0 * r * g4.x + b4.x;
    hv.y += dx1 * r * g4.y + b4.y;
    hv.z += dx2 * r * g4.z + b4.z;
    hv.w += dx3 * r * g4.w + b4.w;
    *(float4*)(h + (size_t)row * EMB + c) = hv;
}

// ---------------- launch ----------------
static float* sym_addr(const void* sym) {
    void* p = nullptr;
    cudaGetSymbolAddress(&p, sym);
    return (float*)p;
}

extern "C" void kernel_launch(void* const* d_in, const int* in_sizes, int n_in,
                              void* d_out, int out_size)
{
    const int*   x   = (const int*)d_in[0];   // int32 tokens
    const float* we  = (const float*)d_in[1];
    const float* pe  = (const float*)d_in[2];
    const float* KQV = (const float*)d_in[3];
    const float* WO  = (const float*)d_in[4];
    const float* Wup = (const float*)d_in[5];
    const float* bup = (const float*)d_in[6];
    const float* Wdn = (const float*)d_in[7];
    const float* bdn = (const float*)d_in[8];
    const float* g1  = (const float*)d_in[9];
    const float* b1  = (const float*)d_in[10];
    const float* g2  = (const float*)d_in[11];
    const float* b2  = (const float*)d_in[12];
    const float* ub  = (const float*)d_in[13];
    float* out = (float*)d_out;

    float* h    = sym_addr(g_h);
    float* qkv  = sym_addr(g_qkv);
    float* attn = sym_addr(g_attn);
    float* tmp  = sym_addr(g_tmp);
    float* ff   = sym_addr(g_ff);

    const int attn_smem = 4 * BQ * LDP * (int)sizeof(float);   // 69632 B
    cudaFuncSetAttribute(flash_attn_kernel,
                         cudaFuncAttributeMaxDynamicSharedMemorySize, attn_smem);

    embed_kernel<<<BS, 256>>>(x, we, pe, h);

    for (int l = 0; l < NL; l++) {
        sgemm_kernel<false, false, false>
            <<<dim3(3 * EMB / TBN, BS / TBM), 256>>>(
                h, KQV + (size_t)l * EMB * 3 * EMB, nullptr, qkv, BS, 3 * EMB, EMB);

        flash_attn_kernel<<<dim3(SEQ / BQ, NH, BATCH), 256, attn_smem>>>(qkv, attn);

        sgemm_kernel<false, false, false>
            <<<dim3(EMB / TBN, BS / TBM), 256>>>(
                attn, WO + (size_t)l * EMB * EMB, nullptr, tmp, BS, EMB, EMB);

        ln_add_kernel<<<BS, 256>>>(tmp, g1 + l * EMB, b1 + l * EMB, h);

        sgemm_kernel<false, true, true>
            <<<dim3(FF / TBN, BS / TBM), 256>>>(
                h, Wup + (size_t)l * EMB * FF, bup + (size_t)l * FF, ff, BS, FF, EMB);

        sgemm_kernel<false, true, false>
            <<<dim3(EMB / TBN, BS / TBM), 256>>>(
                ff, Wdn + (size_t)l * FF * EMB, bdn + (size_t)l * EMB, tmp, BS, EMB, FF);

        ln_add_kernel<<<BS, 256>>>(tmp, g2 + l * EMB, b2 + l * EMB, h);
    }

    sgemm_kernel<true, true, false>
        <<<dim3(VOC / TBN, BS / TBM), 256>>>(h, we, ub, out, BS, VOC, EMB);
}

// round 13
// speedup vs baseline: 5.3100x; 1.5760x over previous
#include <cuda_runtime.h>
#include <cuda_bf16.h>
#include <cstdint>

// Problem constants
#define BATCH 2
#define SEQ   2048
#define EMB   1024
#define NH    16
#define HD    64
#define FF    4096
#define NL    4
#define VOC   32000
#define BS    (BATCH*SEQ)   // 4096 rows

// ---------------- scratch (device globals; no allocation) ----------------
__device__ float g_h   [(size_t)BS * EMB];
__device__ float g_qkv [(size_t)BS * 3 * EMB];
__device__ float g_attn[(size_t)BS * EMB];
__device__ float g_tmp [(size_t)BS * EMB];
__device__ float g_ff  [(size_t)BS * FF];

// bf16 hi/lo split buffers
__device__ __nv_bfloat16 g_ahi[(size_t)BS * FF];
__device__ __nv_bfloat16 g_alo[(size_t)BS * FF];
__device__ __nv_bfloat16 g_wkqv_hi[(size_t)NL * 3 * EMB * EMB];
__device__ __nv_bfloat16 g_wkqv_lo[(size_t)NL * 3 * EMB * EMB];
__device__ __nv_bfloat16 g_wo_hi  [(size_t)NL * EMB * EMB];
__device__ __nv_bfloat16 g_wo_lo  [(size_t)NL * EMB * EMB];
__device__ __nv_bfloat16 g_wup_hi [(size_t)NL * EMB * FF];
__device__ __nv_bfloat16 g_wup_lo [(size_t)NL * EMB * FF];
__device__ __nv_bfloat16 g_wdn_hi [(size_t)NL * FF * EMB];
__device__ __nv_bfloat16 g_wdn_lo [(size_t)NL * FF * EMB];
__device__ __nv_bfloat16 g_we_hi  [(size_t)VOC * EMB];
__device__ __nv_bfloat16 g_we_lo  [(size_t)VOC * EMB];

// ==================== PTX helpers (baseline ISA only, no -a features) ====================
__device__ __forceinline__ uint32_t cvta_smem(const void* p) {
    uint32_t a;
    asm("{ .reg .u64 t; cvta.to.shared.u64 t, %1; cvt.u32.u64 %0, t; }"
        : "=r"(a) : "l"(p));
    return a;
}
__device__ __forceinline__ void cp_async16(uint32_t dst, const void* src) {
    asm volatile("cp.async.cg.shared.global [%0], [%1], 16;" :: "r"(dst), "l"(src));
}
__device__ __forceinline__ void cp_commit() {
    asm volatile("cp.async.commit_group;" ::: "memory");
}
__device__ __forceinline__ void cp_wait1() {
    asm volatile("cp.async.wait_group 1;" ::: "memory");
}
__device__ __forceinline__ void cp_wait0() {
    asm volatile("cp.async.wait_group 0;" ::: "memory");
}
__device__ __forceinline__ void ldmatrix_x4(uint32_t* r, uint32_t addr) {
    asm volatile("ldmatrix.sync.aligned.m8n8.x4.shared.b16 {%0,%1,%2,%3}, [%4];"
                 : "=r"(r[0]), "=r"(r[1]), "=r"(r[2]), "=r"(r[3]) : "r"(addr));
}
__device__ __forceinline__ void mma_bf16(float* c, const uint32_t* a, const uint32_t* b) {
    asm volatile(
        "mma.sync.aligned.m16n8k16.row.col.f32.bf16.bf16.f32 "
        "{%0,%1,%2,%3}, {%4,%5,%6,%7}, {%8,%9}, {%0,%1,%2,%3};"
        : "+f"(c[0]), "+f"(c[1]), "+f"(c[2]), "+f"(c[3])
        : "r"(a[0]), "r"(a[1]), "r"(a[2]), "r"(a[3]), "r"(b[0]), "r"(b[1]));
}

// ==================== conversion kernels ====================
__global__ void __launch_bounds__(256) cvt_kernel(
    const float* __restrict__ in, __nv_bfloat16* __restrict__ hi,
    __nv_bfloat16* __restrict__ lo, size_t n4)
{
    size_t i = (size_t)blockIdx.x * 256 + threadIdx.x;
    if (i >= n4) return;
    float4 v = ((const float4*)in)[i];
    __nv_bfloat16 h0 = __float2bfloat16(v.x);
    __nv_bfloat16 h1 = __float2bfloat16(v.y);
    __nv_bfloat16 h2 = __float2bfloat16(v.z);
    __nv_bfloat16 h3 = __float2bfloat16(v.w);
    __nv_bfloat16 l0 = __float2bfloat16(v.x - __bfloat162float(h0));
    __nv_bfloat16 l1 = __float2bfloat16(v.y - __bfloat162float(h1));
    __nv_bfloat16 l2 = __float2bfloat16(v.z - __bfloat162float(h2));
    __nv_bfloat16 l3 = __float2bfloat16(v.w - __bfloat162float(h3));
    __nv_bfloat162 a, b;
    a.x = h0; a.y = h1; b.x = h2; b.y = h3;
    ((__nv_bfloat162*)hi)[2 * i]     = a;
    ((__nv_bfloat162*)hi)[2 * i + 1] = b;
    a.x = l0; a.y = l1; b.x = l2; b.y = l3;
    ((__nv_bfloat162*)lo)[2 * i]     = a;
    ((__nv_bfloat162*)lo)[2 * i + 1] = b;
}

// fp32 [R][C] -> bf16 hi/lo transposed [C][R]
__global__ void __launch_bounds__(256) cvt_t_kernel(
    const float* __restrict__ in, __nv_bfloat16* __restrict__ hi,
    __nv_bfloat16* __restrict__ lo, int R, int C)
{
    __shared__ float t[32][33];
    const int c0 = blockIdx.x * 32, r0 = blockIdx.y * 32;
    const int tx = threadIdx.x, ty = threadIdx.y;   // 32 x 8
#pragma unroll
    for (int j = 0; j < 32; j += 8)
        t[ty + j][tx] = in[(size_t)(r0 + ty + j) * C + c0 + tx];
    __syncthreads();
#pragma unroll
    for (int j = 0; j < 32; j += 8) {
        float a = t[tx][ty + j];
        __nv_bfloat16 h = __float2bfloat16(a);
        __nv_bfloat16 l = __float2bfloat16(a - __bfloat162float(h));
        size_t o = (size_t)(c0 + ty + j) * R + r0 + tx;
        hi[o] = h; lo[o] = l;
    }
}

// ==================== HMMA bf16 split-3 GEMM ====================
// C(MxN fp32) = A(MxK) @ B(NxK)^T, A/B as hi+lo bf16, both K-major.
// Tile 128x64, K-chunk 64 elems. 8 warps (4M x 2N), warp tile 32x32.
// Stage layout (49152 B): Ahi[0,16K) Alo[16K,32K) Bhi[32K,40K) Blo[40K,48K)
#define GBM 128
#define GBN 64
#define GBK 64
#define STG 49152
#define GEMM_SMEM (2 * STG)

template<bool BIAS, bool RELU>
__device__ __forceinline__ void hgemm_prefetch(
    const __nv_bfloat16* Ahi, const __nv_bfloat16* Alo,
    const __nv_bfloat16* Bhi, const __nv_bfloat16* Blo,
    int K, int m0, int n0, int tid, int k0, uint32_t st)
{
    const int ar = tid >> 1;             // 0..127
    const int as0 = (tid & 1) * 4;       // 0 or 4 (16B slots)
    const int br = tid >> 2;             // 0..63
    const int bs0 = (tid & 3) * 2;       // 0,2,4,6
    const __nv_bfloat16* pAh = Ahi + (size_t)(m0 + ar) * K + k0;
    const __nv_bfloat16* pAl = Alo + (size_t)(m0 + ar) * K + k0;
#pragma unroll
    for (int j = 0; j < 4; j++) {
        int s = as0 + j;
        uint32_t dst = st + ar * 128 + ((s * 16) ^ ((ar & 7) << 4));
        cp_async16(dst,         pAh + s * 8);
        cp_async16(dst + 16384, pAl + s * 8);
    }
    const __nv_bfloat16* pBh = Bhi + (size_t)(n0 + br) * K + k0;
    const __nv_bfloat16* pBl = Blo + (size_t)(n0 + br) * K + k0;
#pragma unroll
    for (int j = 0; j < 2; j++) {
        int s = bs0 + j;
        uint32_t dst = st + 32768 + br * 128 + ((s * 16) ^ ((br & 7) << 4));
        cp_async16(dst,        pBh + s * 8);
        cp_async16(dst + 8192, pBl + s * 8);
    }
}

template<bool BIAS, bool RELU>
__global__ void __launch_bounds__(256, 2) hgemm_kernel(
    const __nv_bfloat16* __restrict__ Ahi, const __nv_bfloat16* __restrict__ Alo,
    const __nv_bfloat16* __restrict__ Bhi, const __nv_bfloat16* __restrict__ Blo,
    const float* __restrict__ bias, float* __restrict__ C,
    int M, int N, int K)
{
    extern __shared__ char sm[];
    const int tid = threadIdx.x;
    const int lane = tid & 31;
    const int warp = tid >> 5;
    const int warpM = warp & 3;          // 0..3
    const int warpN = warp >> 2;         // 0..1
    const int m0 = blockIdx.y * GBM;
    const int n0 = blockIdx.x * GBN;
    const uint32_t sbase = cvta_smem(sm);

    float acc[2][4][4];
#pragma unroll
    for (int i = 0; i < 2; i++)
#pragma unroll
        for (int j = 0; j < 4; j++)
#pragma unroll
            for (int k = 0; k < 4; k++) acc[i][j][k] = 0.f;

    const int nch = K / GBK;

    hgemm_prefetch<BIAS, RELU>(Ahi, Alo, Bhi, Blo, K, m0, n0, tid, 0, sbase);
    cp_commit();

    // ldmatrix lane addressing (precomputed row/col pieces)
    const int a_row_b = warpM * 32 + (lane & 7) + ((lane >> 3) & 1) * 8;  // + mt*16
    const int a_col_b = ((lane >> 4) & 1) * 16;                            // + kk*32
    const int b_row_b = warpN * 32 + (lane & 7) + ((lane >> 4) & 1) * 8;  // + nt2*16
    const int b_col_b = ((lane >> 3) & 1) * 16;                            // + kk*32

    for (int i = 0; i < nch; i++) {
        const int s = i & 1;
        if (i + 1 < nch) {
            hgemm_prefetch<BIAS, RELU>(Ahi, Alo, Bhi, Blo, K, m0, n0, tid,
                                       (i + 1) * GBK, sbase + (s ^ 1) * STG);
            cp_commit();
            cp_wait1();
        } else {
            cp_wait0();
        }
        __syncthreads();

        const uint32_t st = sbase + s * STG;
#pragma unroll
        for (int kk = 0; kk < 4; kk++) {
            uint32_t ah[2][4], al[2][4];
#pragma unroll
            for (int mt = 0; mt < 2; mt++) {
                int row = a_row_b + mt * 16;
                int col = kk * 32 + a_col_b;
                uint32_t addr = st + row * 128 + (col ^ ((row & 7) << 4));
                ldmatrix_x4(ah[mt], addr);
                ldmatrix_x4(al[mt], addr + 16384);
            }
            uint32_t bh[4][2], bl[4][2];
#pragma unroll
            for (int nt2 = 0; nt2 < 2; nt2++) {
                int row = b_row_b + nt2 * 16;
                int col = kk * 32 + b_col_b;
                uint32_t addr = st + 32768 + row * 128 + (col ^ ((row & 7) << 4));
                uint32_t r[4];
                ldmatrix_x4(r, addr);
                bh[nt2 * 2][0] = r[0]; bh[nt2 * 2][1] = r[1];
                bh[nt2 * 2 + 1][0] = r[2]; bh[nt2 * 2 + 1][1] = r[3];
                ldmatrix_x4(r, addr + 8192);
                bl[nt2 * 2][0] = r[0]; bl[nt2 * 2][1] = r[1];
                bl[nt2 * 2 + 1][0] = r[2]; bl[nt2 * 2 + 1][1] = r[3];
            }
#pragma unroll
            for (int mt = 0; mt < 2; mt++)
#pragma unroll
                for (int nt = 0; nt < 4; nt++) mma_bf16(acc[mt][nt], ah[mt], bh[nt]);
#pragma unroll
            for (int mt = 0; mt < 2; mt++)
#pragma unroll
                for (int nt = 0; nt < 4; nt++) mma_bf16(acc[mt][nt], ah[mt], bl[nt]);
#pragma unroll
            for (int mt = 0; mt < 2; mt++)
#pragma unroll
                for (int nt = 0; nt < 4; nt++) mma_bf16(acc[mt][nt], al[mt], bh[nt]);
        }
        __syncthreads();
    }

    // ---- epilogue ----
    const int er = lane >> 2;            // 0..7
    const int ec = (lane & 3) * 2;       // 0,2,4,6
#pragma unroll
    for (int mt = 0; mt < 2; mt++) {
#pragma unroll
        for (int nt = 0; nt < 4; nt++) {
            int col = n0 + warpN * 32 + nt * 8 + ec;
            float bx = 0.f, by = 0.f;
            if (BIAS) { bx = bias[col]; by = bias[col + 1]; }
            int row0 = m0 + warpM * 32 + mt * 16 + er;
            float2 v0 = { acc[mt][nt][0] + bx, acc[mt][nt][1] + by };
            float2 v1 = { acc[mt][nt][2] + bx, acc[mt][nt][3] + by };
            if (RELU) {
                v0.x = fmaxf(v0.x, 0.f); v0.y = fmaxf(v0.y, 0.f);
                v1.x = fmaxf(v1.x, 0.f); v1.y = fmaxf(v1.y, 0.f);
            }
            *(float2*)(C + (size_t)row0 * N + col)       = v0;
            *(float2*)(C + (size_t)(row0 + 8) * N + col) = v1;
        }
    }
}

// ==================== embed ====================
__global__ void __launch_bounds__(256) embed_kernel(
    const int* __restrict__ x, const float* __restrict__ we,
    const float* __restrict__ pe, float* __restrict__ h)
{
    int row = blockIdx.x;
    int s   = row % SEQ;
    int tok = x[row];
    int c = threadIdx.x * 4;
    float4 a = *(const float4*)(we + (size_t)tok * EMB + c);
    float4 b = *(const float4*)(pe + (size_t)s   * EMB + c);
    float4 o; o.x = a.x + b.x; o.y = a.y + b.y; o.z = a.z + b.z; o.w = a.w + b.w;
    *(float4*)(h + (size_t)row * EMB + c) = o;
}

// ==================== flash attention (R9-validated) ====================
#define BQ 64
#define BK 64
#define LDP 68

__global__ void __launch_bounds__(256) flash_attn_kernel(
    const float* __restrict__ qkv, float* __restrict__ out)
{
    extern __shared__ float smem[];
    float (*Qs)[LDP] = (float(*)[LDP])smem;
    float (*Ks)[LDP] = (float(*)[LDP])(smem + BQ * LDP);
    float (*Vs)[LDP] = (float(*)[LDP])(smem + 2 * BQ * LDP);
    float (*Ps)[LDP] = (float(*)[LDP])(smem + 3 * BQ * LDP);

    const int qt = gridDim.x - 1 - blockIdx.x;   // longest blocks first
    const int h  = blockIdx.y;
    const int b  = blockIdx.z;
    const int tid = threadIdx.x;

    const float* base = qkv + (size_t)b * SEQ * (3 * EMB) + h * (3 * HD);

    {
        const int rr = tid >> 4;
        const int cc = (tid & 15) * 4;
#pragma unroll
        for (int p = 0; p < 4; p++) {
            int r = p * 16 + rr;
            *(float4*)&Qs[r][cc] =
                *(const float4*)(base + (size_t)(qt * BQ + r) * (3 * EMB) + HD + cc);
        }
    }
    __syncthreads();

    const int r  = tid >> 2;
    const int g  = tid & 3;
    const int ds = g * 16;
    const int q_global = qt * BQ + r;

    float m = -1e30f, l = 0.f;
    float o[16];
#pragma unroll
    for (int i = 0; i < 16; i++) o[i] = 0.f;

    const int nkt = qt + 1;

    for (int kt = 0; kt < nkt; kt++) {
        {
            const int rr = tid >> 4;
            const int cc = (tid & 15) * 4;
#pragma unroll
            for (int p = 0; p < 4; p++) {
                int rk = p * 16 + rr;
                const float* src = base + (size_t)(kt * BK + rk) * (3 * EMB);
                *(float4*)&Ks[rk][cc] = *(const float4*)(src + cc);
                *(float4*)&Vs[rk][cc] = *(const float4*)(src + 2 * HD + cc);
            }
        }
        __syncthreads();

        float s[16];
#pragma unroll
        for (int i = 0; i < 16; i++) s[i] = 0.f;
#pragma unroll
        for (int dd = 0; dd < HD; dd += 4) {
            float4 q4 = *(const float4*)&Qs[r][dd];
#pragma unroll
            for (int i = 0; i < 16; i++) {
                float4 k4 = *(const float4*)&Ks[g + 4 * i][dd];
                s[i] = fmaf(q4.x, k4.x, fmaf(q4.y, k4.y,
                       fmaf(q4.z, k4.z, fmaf(q4.w, k4.w, s[i]))));
            }
        }
        const bool diag = (kt == qt);
#pragma unroll
        for (int i = 0; i < 16; i++) {
            s[i] *= 0.125f;
            if (diag && (kt * BK + g + 4 * i) > q_global) s[i] = -1e30f;
        }

        float lm = s[0];
#pragma unroll
        for (int i = 1; i < 16; i++) lm = fmaxf(lm, s[i]);
        lm = fmaxf(lm, __shfl_xor_sync(0xffffffffu, lm, 1));
        lm = fmaxf(lm, __shfl_xor_sync(0xffffffffu, lm, 2));
        const float mnew = fmaxf(m, lm);
        const float corr = __expf(m - mnew);
        float psum = 0.f;
#pragma unroll
        for (int i = 0; i < 16; i++) {
            float p = __expf(s[i] - mnew);
            Ps[r][g + 4 * i] = p;
            psum += p;
        }
        psum += __shfl_xor_sync(0xffffffffu, psum, 1);
        psum += __shfl_xor_sync(0xffffffffu, psum, 2);
        l = l * corr + psum;
        m = mnew;
#pragma unroll
        for (int i = 0; i < 16; i++) o[i] *= corr;
        __syncwarp();

#pragma unroll 8
        for (int k = 0; k < BK; k++) {
            float p = Ps[r][k];
            float4 v0 = *(const float4*)&Vs[k][ds];
            float4 v1 = *(const float4*)&Vs[k][ds + 4];
            float4 v2 = *(const float4*)&Vs[k][ds + 8];
            float4 v3 = *(const float4*)&Vs[k][ds + 12];
            o[0]  = fmaf(p, v0.x, o[0]);  o[1]  = fmaf(p, v0.y, o[1]);
            o[2]  = fmaf(p, v0.z, o[2]);  o[3]  = fmaf(p, v0.w, o[3]);
            o[4]  = fmaf(p, v1.x, o[4]);  o[5]  = fmaf(p, v1.y, o[5]);
            o[6]  = fmaf(p, v1.z, o[6]);  o[7]  = fmaf(p, v1.w, o[7]);
            o[8]  = fmaf(p, v2.x, o[8]);  o[9]  = fmaf(p, v2.y, o[9]);
            o[10] = fmaf(p, v2.z, o[10]); o[11] = fmaf(p, v2.w, o[11]);
            o[12] = fmaf(p, v3.x, o[12]); o[13] = fmaf(p, v3.y, o[13]);
            o[14] = fmaf(p, v3.z, o[14]); o[15] = fmaf(p, v3.w, o[15]);
        }
        __syncthreads();
    }

    const float inv = 1.f / l;
    float* op = out + (size_t)(b * SEQ + q_global) * EMB + h * HD + ds;
#pragma unroll
    for (int i = 0; i < 16; i += 4) {
        float4 v = { o[i] * inv, o[i+1] * inv, o[i+2] * inv, o[i+3] * inv };
        *(float4*)(op + i) = v;
    }
}

// ==================== fused LayerNorm + residual ====================
__global__ void __launch_bounds__(256) ln_add_kernel(
    const float* __restrict__ x, const float* __restrict__ gam,
    const float* __restrict__ bet, float* __restrict__ h)
{
    const int row = blockIdx.x;
    const int tid = threadIdx.x;
    __shared__ float red[8];
    __shared__ float stats[2];

    const float* xr = x + (size_t)row * EMB;
    const int c = tid * 4;
    float4 v = *(const float4*)(xr + c);
    float s = v.x + v.y + v.z + v.w;
#pragma unroll
    for (int o = 16; o; o >>= 1) s += __shfl_xor_sync(0xffffffffu, s, o);
    if ((tid & 31) == 0) red[tid >> 5] = s;
    __syncthreads();
    if (tid == 0) {
        float t = 0.f;
#pragma unroll
        for (int i = 0; i < 8; i++) t += red[i];
        stats[0] = t * (1.f / EMB);
    }
    __syncthreads();
    const float mu = stats[0];

    float dx0 = v.x - mu, dx1 = v.y - mu, dx2 = v.z - mu, dx3 = v.w - mu;
    float sq = dx0 * dx0 + dx1 * dx1 + dx2 * dx2 + dx3 * dx3;
#pragma unroll
    for (int o = 16; o; o >>= 1) sq += __shfl_xor_sync(0xffffffffu, sq, o);
    if ((tid & 31) == 0) red[tid >> 5] = sq;
    __syncthreads();
    if (tid == 0) {
        float t = 0.f;
#pragma unroll
        for (int i = 0; i < 8; i++) t += red[i];
        stats[1] = rsqrtf(t * (1.f / EMB) + 1e-6f);
    }
    __syncthreads();
    const float r = stats[1];

    float4 g4 = *(const float4*)(gam + c);
    float4 b4 = *(const float4*)(bet + c);
    float4 hv = *(float4*)(h + (size_t)row * EMB + c);
    hv.x += dx0 * r * g4.x + b4.x;
    hv.y += dx1 * r * g4.y + b4.y;
    hv.z += dx2 * r * g4.z + b4.z;
    hv.w += dx3 * r * g4.w + b4.w;
    *(float4*)(h + (size_t)row * EMB + c) = hv;
}

// ==================== host launch ====================
static void* sym_addr(const void* sym) {
    void* p = nullptr;
    cudaGetSymbolAddress(&p, sym);
    return p;
}

extern "C" void kernel_launch(void* const* d_in, const int* in_sizes, int n_in,
                              void* d_out, int out_size)
{
    const int*   x   = (const int*)d_in[0];
    const float* we  = (const float*)d_in[1];
    const float* pe  = (const float*)d_in[2];
    const float* KQV = (const float*)d_in[3];
    const float* WO  = (const float*)d_in[4];
    const float* Wup = (const float*)d_in[5];
    const float* bup = (const float*)d_in[6];
    const float* Wdn = (const float*)d_in[7];
    const float* bdn = (const float*)d_in[8];
    const float* g1  = (const float*)d_in[9];
    const float* b1  = (const float*)d_in[10];
    const float* g2  = (const float*)d_in[11];
    const float* b2  = (const float*)d_in[12];
    const float* ub  = (const float*)d_in[13];
    float* out = (float*)d_out;

    float* h    = (float*)sym_addr(g_h);
    float* qkv  = (float*)sym_addr(g_qkv);
    float* attn = (float*)sym_addr(g_attn);
    float* tmp  = (float*)sym_addr(g_tmp);
    float* ff   = (float*)sym_addr(g_ff);
    __nv_bfloat16* ahi = (__nv_bfloat16*)sym_addr(g_ahi);
    __nv_bfloat16* alo = (__nv_bfloat16*)sym_addr(g_alo);
    __nv_bfloat16* wkqv_h = (__nv_bfloat16*)sym_addr(g_wkqv_hi);
    __nv_bfloat16* wkqv_l = (__nv_bfloat16*)sym_addr(g_wkqv_lo);
    __nv_bfloat16* wo_h   = (__nv_bfloat16*)sym_addr(g_wo_hi);
    __nv_bfloat16* wo_l   = (__nv_bfloat16*)sym_addr(g_wo_lo);
    __nv_bfloat16* wup_h  = (__nv_bfloat16*)sym_addr(g_wup_hi);
    __nv_bfloat16* wup_l  = (__nv_bfloat16*)sym_addr(g_wup_lo);
    __nv_bfloat16* wdn_h  = (__nv_bfloat16*)sym_addr(g_wdn_hi);
    __nv_bfloat16* wdn_l  = (__nv_bfloat16*)sym_addr(g_wdn_lo);
    __nv_bfloat16* we_h   = (__nv_bfloat16*)sym_addr(g_we_hi);
    __nv_bfloat16* we_l   = (__nv_bfloat16*)sym_addr(g_we_lo);

    cudaFuncSetAttribute(hgemm_kernel<false, false>,
                         cudaFuncAttributeMaxDynamicSharedMemorySize, GEMM_SMEM);
    cudaFuncSetAttribute(hgemm_kernel<true, true>,
                         cudaFuncAttributeMaxDynamicSharedMemorySize, GEMM_SMEM);
    cudaFuncSetAttribute(hgemm_kernel<true, false>,
                         cudaFuncAttributeMaxDynamicSharedMemorySize, GEMM_SMEM);
    const int attn_smem = 4 * BQ * LDP * (int)sizeof(float);
    cudaFuncSetAttribute(flash_attn_kernel,
                         cudaFuncAttributeMaxDynamicSharedMemorySize, attn_smem);

    // ---- weight conversion (transpose to [N][K] + hi/lo split) ----
    dim3 tb(32, 8);
    for (int l = 0; l < NL; l++) {
        cvt_t_kernel<<<dim3(3 * EMB / 32, EMB / 32), tb>>>(
            KQV + (size_t)l * EMB * 3 * EMB,
            wkqv_h + (size_t)l * 3 * EMB * EMB, wkqv_l + (size_t)l * 3 * EMB * EMB,
            EMB, 3 * EMB);
        cvt_t_kernel<<<dim3(EMB / 32, EMB / 32), tb>>>(
            WO + (size_t)l * EMB * EMB,
            wo_h + (size_t)l * EMB * EMB, wo_l + (size_t)l * EMB * EMB,
            EMB, EMB);
        cvt_t_kernel<<<dim3(FF / 32, EMB / 32), tb>>>(
            Wup + (size_t)l * EMB * FF,
            wup_h + (size_t)l * (size_t)EMB * FF, wup_l + (size_t)l * (size_t)EMB * FF,
            EMB, FF);
        cvt_t_kernel<<<dim3(EMB / 32, FF / 32), tb>>>(
            Wdn + (size_t)l * FF * EMB,
            wdn_h + (size_t)l * (size_t)FF * EMB, wdn_l + (size_t)l * (size_t)FF * EMB,
            FF, EMB);
    }
    // word_embed is already [VOC][EMB] = [N][K]
    cvt_kernel<<<(unsigned)((size_t)VOC * EMB / 4 / 256), 256>>>(
        we, we_h, we_l, (size_t)VOC * EMB / 4);

    embed_kernel<<<BS, 256>>>(x, we, pe, h);

    const unsigned cvtE  = (unsigned)((size_t)BS * EMB / 4 / 256);
    const unsigned cvtF  = (unsigned)((size_t)BS * FF  / 4 / 256);

    for (int l = 0; l < NL; l++) {
        // qkv = h @ KQV[l]
        cvt_kernel<<<cvtE, 256>>>(h, ahi, alo, (size_t)BS * EMB / 4);
        hgemm_kernel<false, false>
            <<<dim3(3 * EMB / GBN, BS / GBM), 256, GEMM_SMEM>>>(
                ahi, alo,
                wkqv_h + (size_t)l * 3 * EMB * EMB, wkqv_l + (size_t)l * 3 * EMB * EMB,
                nullptr, qkv, BS, 3 * EMB, EMB);

        flash_attn_kernel<<<dim3(SEQ / BQ, NH, BATCH), 256, attn_smem>>>(qkv, attn);

        // tmp = attn @ WO[l]
        cvt_kernel<<<cvtE, 256>>>(attn, ahi, alo, (size_t)BS * EMB / 4);
        hgemm_kernel<false, false>
            <<<dim3(EMB / GBN, BS / GBM), 256, GEMM_SMEM>>>(
                ahi, alo,
                wo_h + (size_t)l * EMB * EMB, wo_l + (size_t)l * EMB * EMB,
                nullptr, tmp, BS, EMB, EMB);

        ln_add_kernel<<<BS, 256>>>(tmp, g1 + l * EMB, b1 + l * EMB, h);

        // ff = relu(h @ W_up[l] + b_up[l])
        cvt_kernel<<<cvtE, 256>>>(h, ahi, alo, (size_t)BS * EMB / 4);
        hgemm_kernel<true, true>
            <<<dim3(FF / GBN, BS / GBM), 256, GEMM_SMEM>>>(
                ahi, alo,
                wup_h + (size_t)l * (size_t)EMB * FF, wup_l + (size_t)l * (size_t)EMB * FF,
                bup + (size_t)l * FF, ff, BS, FF, EMB);

        // tmp = ff @ W_down[l] + b_down[l]
        cvt_kernel<<<cvtF, 256>>>(ff, ahi, alo, (size_t)BS * FF / 4);
        hgemm_kernel<true, false>
            <<<dim3(EMB / GBN, BS / GBM), 256, GEMM_SMEM>>>(
                ahi, alo,
                wdn_h + (size_t)l * (size_t)FF * EMB, wdn_l + (size_t)l * (size_t)FF * EMB,
                bdn + (size_t)l * EMB, tmp, BS, EMB, FF);

        ln_add_kernel<<<BS, 256>>>(tmp, g2 + l * EMB, b2 + l * EMB, h);
    }

    // logits = h @ we^T + unembed_b
    cvt_kernel<<<cvtE, 256>>>(h, ahi, alo, (size_t)BS * EMB / 4);
    hgemm_kernel<true, false>
        <<<dim3(VOC / GBN, BS / GBM), 256, GEMM_SMEM>>>(
            ahi, alo, we_h, we_l, ub, out, BS, VOC, EMB);
}

// round 15
// speedup vs baseline: 9.6783x; 1.8226x over previous
#include <cuda_runtime.h>
#include <cuda_bf16.h>
#include <cstdint>

// Problem constants
#define BATCH 2
#define SEQ   2048
#define EMB   1024
#define NH    16
#define HD    64
#define FF    4096
#define NL    4
#define VOC   32000
#define BS    (BATCH*SEQ)   // 4096 rows

// ---------------- scratch (device globals; no allocation) ----------------
__device__ float g_h   [(size_t)BS * EMB];
__device__ float g_qkv [(size_t)BS * 3 * EMB];
__device__ float g_attn[(size_t)BS * EMB];
__device__ float g_tmp [(size_t)BS * EMB];
__device__ float g_ff  [(size_t)BS * FF];

// bf16 hi/lo split buffers
__device__ __nv_bfloat16 g_ahi[(size_t)BS * FF];
__device__ __nv_bfloat16 g_alo[(size_t)BS * FF];
__device__ __nv_bfloat16 g_qkvh[(size_t)BS * 3 * EMB];
__device__ __nv_bfloat16 g_qkvl[(size_t)BS * 3 * EMB];
__device__ __nv_bfloat16 g_wkqv_hi[(size_t)NL * 3 * EMB * EMB];
__device__ __nv_bfloat16 g_wkqv_lo[(size_t)NL * 3 * EMB * EMB];
__device__ __nv_bfloat16 g_wo_hi  [(size_t)NL * EMB * EMB];
__device__ __nv_bfloat16 g_wo_lo  [(size_t)NL * EMB * EMB];
__device__ __nv_bfloat16 g_wup_hi [(size_t)NL * EMB * FF];
__device__ __nv_bfloat16 g_wup_lo [(size_t)NL * EMB * FF];
__device__ __nv_bfloat16 g_wdn_hi [(size_t)NL * FF * EMB];
__device__ __nv_bfloat16 g_wdn_lo [(size_t)NL * FF * EMB];
__device__ __nv_bfloat16 g_we_hi  [(size_t)VOC * EMB];
__device__ __nv_bfloat16 g_we_lo  [(size_t)VOC * EMB];

// ==================== PTX helpers (baseline ISA only) ====================
__device__ __forceinline__ uint32_t cvta_smem(const void* p) {
    uint32_t a;
    asm("{ .reg .u64 t; cvta.to.shared.u64 t, %1; cvt.u32.u64 %0, t; }"
        : "=r"(a) : "l"(p));
    return a;
}
__device__ __forceinline__ void cp_async16(uint32_t dst, const void* src) {
    asm volatile("cp.async.cg.shared.global [%0], [%1], 16;" :: "r"(dst), "l"(src));
}
__device__ __forceinline__ void cp_commit() {
    asm volatile("cp.async.commit_group;" ::: "memory");
}
__device__ __forceinline__ void cp_wait1() {
    asm volatile("cp.async.wait_group 1;" ::: "memory");
}
__device__ __forceinline__ void cp_wait0() {
    asm volatile("cp.async.wait_group 0;" ::: "memory");
}
__device__ __forceinline__ void ldmatrix_x4(uint32_t* r, uint32_t addr) {
    asm volatile("ldmatrix.sync.aligned.m8n8.x4.shared.b16 {%0,%1,%2,%3}, [%4];"
                 : "=r"(r[0]), "=r"(r[1]), "=r"(r[2]), "=r"(r[3]) : "r"(addr));
}
__device__ __forceinline__ void ldmatrix_x4_t(uint32_t* r, uint32_t addr) {
    asm volatile("ldmatrix.sync.aligned.m8n8.x4.trans.shared.b16 {%0,%1,%2,%3}, [%4];"
                 : "=r"(r[0]), "=r"(r[1]), "=r"(r[2]), "=r"(r[3]) : "r"(addr));
}
__device__ __forceinline__ void mma_bf16(float* c, const uint32_t* a, const uint32_t* b) {
    asm volatile(
        "mma.sync.aligned.m16n8k16.row.col.f32.bf16.bf16.f32 "
        "{%0,%1,%2,%3}, {%4,%5,%6,%7}, {%8,%9}, {%0,%1,%2,%3};"
        : "+f"(c[0]), "+f"(c[1]), "+f"(c[2]), "+f"(c[3])
        : "r"(a[0]), "r"(a[1]), "r"(a[2]), "r"(a[3]), "r"(b[0]), "r"(b[1]));
}
__device__ __forceinline__ void sts32(uint32_t addr, uint32_t v) {
    asm volatile("st.shared.b32 [%0], %1;" :: "r"(addr), "r"(v) : "memory");
}
__device__ __forceinline__ void split_pack(float a, float b, uint32_t& hi, uint32_t& lo) {
    __nv_bfloat16 ha = __float2bfloat16(a), hb = __float2bfloat16(b);
    __nv_bfloat16 la = __float2bfloat16(a - __bfloat162float(ha));
    __nv_bfloat16 lb = __float2bfloat16(b - __bfloat162float(hb));
    __nv_bfloat162 H; H.x = ha; H.y = hb;
    __nv_bfloat162 L; L.x = la; L.y = lb;
    hi = *(uint32_t*)&H; lo = *(uint32_t*)&L;
}

// ==================== conversion kernels ====================
__global__ void __launch_bounds__(256) cvt_kernel(
    const float* __restrict__ in, __nv_bfloat16* __restrict__ hi,
    __nv_bfloat16* __restrict__ lo, size_t n4)
{
    size_t i = (size_t)blockIdx.x * 256 + threadIdx.x;
    if (i >= n4) return;
    float4 v = ((const float4*)in)[i];
    __nv_bfloat16 h0 = __float2bfloat16(v.x);
    __nv_bfloat16 h1 = __float2bfloat16(v.y);
    __nv_bfloat16 h2 = __float2bfloat16(v.z);
    __nv_bfloat16 h3 = __float2bfloat16(v.w);
    __nv_bfloat16 l0 = __float2bfloat16(v.x - __bfloat162float(h0));
    __nv_bfloat16 l1 = __float2bfloat16(v.y - __bfloat162float(h1));
    __nv_bfloat16 l2 = __float2bfloat16(v.z - __bfloat162float(h2));
    __nv_bfloat16 l3 = __float2bfloat16(v.w - __bfloat162float(h3));
    __nv_bfloat162 a, b;
    a.x = h0; a.y = h1; b.x = h2; b.y = h3;
    ((__nv_bfloat162*)hi)[2 * i]     = a;
    ((__nv_bfloat162*)hi)[2 * i + 1] = b;
    a.x = l0; a.y = l1; b.x = l2; b.y = l3;
    ((__nv_bfloat162*)lo)[2 * i]     = a;
    ((__nv_bfloat162*)lo)[2 * i + 1] = b;
}

// fp32 [R][C] -> bf16 hi/lo transposed [C][R]
__global__ void __launch_bounds__(256) cvt_t_kernel(
    const float* __restrict__ in, __nv_bfloat16* __restrict__ hi,
    __nv_bfloat16* __restrict__ lo, int R, int C)
{
    __shared__ float t[32][33];
    const int c0 = blockIdx.x * 32, r0 = blockIdx.y * 32;
    const int tx = threadIdx.x, ty = threadIdx.y;   // 32 x 8
#pragma unroll
    for (int j = 0; j < 32; j += 8)
        t[ty + j][tx] = in[(size_t)(r0 + ty + j) * C + c0 + tx];
    __syncthreads();
#pragma unroll
    for (int j = 0; j < 32; j += 8) {
        float a = t[tx][ty + j];
        __nv_bfloat16 h = __float2bfloat16(a);
        __nv_bfloat16 l = __float2bfloat16(a - __bfloat162float(h));
        size_t o = (size_t)(c0 + ty + j) * R + r0 + tx;
        hi[o] = h; lo[o] = l;
    }
}

// ==================== HMMA bf16 split-3 GEMM (R13-proven) ====================
#define GBM 128
#define GBN 64
#define GBK 64
#define STG 49152
#define GEMM_SMEM (2 * STG)

__device__ __forceinline__ void hgemm_prefetch(
    const __nv_bfloat16* Ahi, const __nv_bfloat16* Alo,
    const __nv_bfloat16* Bhi, const __nv_bfloat16* Blo,
    int K, int m0, int n0, int tid, int k0, uint32_t st)
{
    const int ar = tid >> 1;
    const int as0 = (tid & 1) * 4;
    const int br = tid >> 2;
    const int bs0 = (tid & 3) * 2;
    const __nv_bfloat16* pAh = Ahi + (size_t)(m0 + ar) * K + k0;
    const __nv_bfloat16* pAl = Alo + (size_t)(m0 + ar) * K + k0;
#pragma unroll
    for (int j = 0; j < 4; j++) {
        int s = as0 + j;
        uint32_t dst = st + ar * 128 + ((s * 16) ^ ((ar & 7) << 4));
        cp_async16(dst,         pAh + s * 8);
        cp_async16(dst + 16384, pAl + s * 8);
    }
    const __nv_bfloat16* pBh = Bhi + (size_t)(n0 + br) * K + k0;
    const __nv_bfloat16* pBl = Blo + (size_t)(n0 + br) * K + k0;
#pragma unroll
    for (int j = 0; j < 2; j++) {
        int s = bs0 + j;
        uint32_t dst = st + 32768 + br * 128 + ((s * 16) ^ ((br & 7) << 4));
        cp_async16(dst,        pBh + s * 8);
        cp_async16(dst + 8192, pBl + s * 8);
    }
}

template<bool BIAS, bool RELU>
__global__ void __launch_bounds__(256, 2) hgemm_kernel(
    const __nv_bfloat16* __restrict__ Ahi, const __nv_bfloat16* __restrict__ Alo,
    const __nv_bfloat16* __restrict__ Bhi, const __nv_bfloat16* __restrict__ Blo,
    const float* __restrict__ bias, float* __restrict__ C,
    int M, int N, int K)
{
    extern __shared__ char sm[];
    const int tid = threadIdx.x;
    const int lane = tid & 31;
    const int warp = tid >> 5;
    const int warpM = warp & 3;
    const int warpN = warp >> 2;
    const int m0 = blockIdx.y * GBM;
    const int n0 = blockIdx.x * GBN;
    const uint32_t sbase = cvta_smem(sm);

    float acc[2][4][4];
#pragma unroll
    for (int i = 0; i < 2; i++)
#pragma unroll
        for (int j = 0; j < 4; j++)
#pragma unroll
            for (int k = 0; k < 4; k++) acc[i][j][k] = 0.f;

    const int nch = K / GBK;

    hgemm_prefetch(Ahi, Alo, Bhi, Blo, K, m0, n0, tid, 0, sbase);
    cp_commit();

    const int a_row_b = warpM * 32 + (lane & 7) + ((lane >> 3) & 1) * 8;
    const int a_col_b = ((lane >> 4) & 1) * 16;
    const int b_row_b = warpN * 32 + (lane & 7) + ((lane >> 4) & 1) * 8;
    const int b_col_b = ((lane >> 3) & 1) * 16;

    for (int i = 0; i < nch; i++) {
        const int s = i & 1;
        if (i + 1 < nch) {
            hgemm_prefetch(Ahi, Alo, Bhi, Blo, K, m0, n0, tid,
                           (i + 1) * GBK, sbase + (s ^ 1) * STG);
            cp_commit();
            cp_wait1();
        } else {
            cp_wait0();
        }
        __syncthreads();

        const uint32_t st = sbase + s * STG;
#pragma unroll
        for (int kk = 0; kk < 4; kk++) {
            uint32_t ah[2][4], al[2][4];
#pragma unroll
            for (int mt = 0; mt < 2; mt++) {
                int row = a_row_b + mt * 16;
                int col = kk * 32 + a_col_b;
                uint32_t addr = st + row * 128 + (col ^ ((row & 7) << 4));
                ldmatrix_x4(ah[mt], addr);
                ldmatrix_x4(al[mt], addr + 16384);
            }
            uint32_t bh[4][2], bl[4][2];
#pragma unroll
            for (int nt2 = 0; nt2 < 2; nt2++) {
                int row = b_row_b + nt2 * 16;
                int col = kk * 32 + b_col_b;
                uint32_t addr = st + 32768 + row * 128 + (col ^ ((row & 7) << 4));
                uint32_t r[4];
                ldmatrix_x4(r, addr);
                bh[nt2 * 2][0] = r[0]; bh[nt2 * 2][1] = r[1];
                bh[nt2 * 2 + 1][0] = r[2]; bh[nt2 * 2 + 1][1] = r[3];
                ldmatrix_x4(r, addr + 8192);
                bl[nt2 * 2][0] = r[0]; bl[nt2 * 2][1] = r[1];
                bl[nt2 * 2 + 1][0] = r[2]; bl[nt2 * 2 + 1][1] = r[3];
            }
#pragma unroll
            for (int mt = 0; mt < 2; mt++)
#pragma unroll
                for (int nt = 0; nt < 4; nt++) mma_bf16(acc[mt][nt], ah[mt], bh[nt]);
#pragma unroll
            for (int mt = 0; mt < 2; mt++)
#pragma unroll
                for (int nt = 0; nt < 4; nt++) mma_bf16(acc[mt][nt], ah[mt], bl[nt]);
#pragma unroll
            for (int mt = 0; mt < 2; mt++)
#pragma unroll
                for (int nt = 0; nt < 4; nt++) mma_bf16(acc[mt][nt], al[mt], bh[nt]);
        }
        __syncthreads();
    }

    const int er = lane >> 2;
    const int ec = (lane & 3) * 2;
#pragma unroll
    for (int mt = 0; mt < 2; mt++) {
#pragma unroll
        for (int nt = 0; nt < 4; nt++) {
            int col = n0 + warpN * 32 + nt * 8 + ec;
            float bx = 0.f, by = 0.f;
            if (BIAS) { bx = bias[col]; by = bias[col + 1]; }
            int row0 = m0 + warpM * 32 + mt * 16 + er;
            float2 v0 = { acc[mt][nt][0] + bx, acc[mt][nt][1] + by };
            float2 v1 = { acc[mt][nt][2] + bx, acc[mt][nt][3] + by };
            if (RELU) {
                v0.x = fmaxf(v0.x, 0.f); v0.y = fmaxf(v0.y, 0.f);
                v1.x = fmaxf(v1.x, 0.f); v1.y = fmaxf(v1.y, 0.f);
            }
            *(float2*)(C + (size_t)row0 * N + col)       = v0;
            *(float2*)(C + (size_t)(row0 + 8) * N + col) = v1;
        }
    }
}

// ==================== tensor-core flash attention ====================
// Block: 64 q-rows x (head, batch). 4 warps, warp w owns q-rows w*16..w*16+15.
// qkv (hi/lo bf16) layout: [(b*SEQ+s)*3E + h*192 + {K:0, Q:64, V:128} + d]
// smem: Qhi(8K) Qlo(8K) | stage0: Kh,Kl,Vh,Vl (4x8K) | stage1 | Phi(8K) Plo(8K)
#define FA_SMEM 98304

__global__ void __launch_bounds__(128, 2) flash_mma_kernel(
    const __nv_bfloat16* __restrict__ qh_g, const __nv_bfloat16* __restrict__ ql_g,
    float* __restrict__ out)
{
    extern __shared__ char sm[];
    const uint32_t sb = cvta_smem(sm);
    const int tid = threadIdx.x;
    const int lane = tid & 31;
    const int w = tid >> 5;
    const int qt = gridDim.x - 1 - blockIdx.x;   // longest first
    const int h = blockIdx.y;
    const int b = blockIdx.z;

    const uint32_t QH = sb, QL = sb + 8192;
    const uint32_t ST0 = sb + 16384;              // stage stride 32768
    const uint32_t PH = sb + 81920;               // PL = PH + 8192

    const size_t rowbase = (size_t)b * SEQ * (3 * EMB);
    const int hoff = h * (3 * HD);

    // ---- Q tile load (hi/lo) ----
    {
        const int r = tid >> 1;
        const int s0 = (tid & 1) * 4;
        const __nv_bfloat16* srcH = qh_g + rowbase + (size_t)(qt * 64 + r) * (3 * EMB) + hoff + HD;
        const __nv_bfloat16* srcL = ql_g + rowbase + (size_t)(qt * 64 + r) * (3 * EMB) + hoff + HD;
#pragma unroll
        for (int j = 0; j < 4; j++) {
            uint32_t o = r * 128 + (((s0 + j) * 16) ^ ((r & 7) << 4));
            cp_async16(QH + o, srcH + (s0 + j) * 8);
            cp_async16(QL + o, srcL + (s0 + j) * 8);
        }
    }
    cp_commit();

    // K/V prefetch into stage
    const int pr = tid >> 1;
    const int ps0 = (tid & 1) * 4;
    const uint32_t prow = pr * 128;

#define PREFETCH_KV(kt_, stg_) do {                                              \
    const __nv_bfloat16* bH = qh_g + rowbase + (size_t)((kt_) * 64 + pr) * (3 * EMB) + hoff; \
    const __nv_bfloat16* bL = ql_g + rowbase + (size_t)((kt_) * 64 + pr) * (3 * EMB) + hoff; \
    _Pragma("unroll")                                                            \
    for (int j = 0; j < 4; j++) {                                                \
        uint32_t o = prow + (((ps0 + j) * 16) ^ ((pr & 7) << 4));                \
        cp_async16((stg_) + o,         bH + (ps0 + j) * 8);                      \
        cp_async16((stg_) + 8192 + o,  bL + (ps0 + j) * 8);                      \
        cp_async16((stg_) + 16384 + o, bH + 128 + (ps0 + j) * 8);                \
        cp_async16((stg_) + 24576 + o, bL + 128 + (ps0 + j) * 8);                \
    } } while (0)

    PREFETCH_KV(0, ST0);
    cp_commit();

    // fragment addressing
    const int row_a = w * 16 + (lane & 15);
    const uint32_t colg_a = ((lane >> 4) & 1) * 16;
    const int row_kb = (lane & 7) + ((lane >> 4) & 1) * 8;   // + ntp*16
    const uint32_t col_kb = ((lane >> 3) & 1) * 16;          // + kk*32
    const int row_v = (lane & 7) + ((lane >> 3) & 1) * 8;    // + kk2*16
    const uint32_t col_v = ((lane >> 4) & 1) * 16;           // + ntp*32

    const int er = lane >> 2, ec = (lane & 3) * 2;
    const int q0 = qt * 64 + w * 16 + er;                    // rows q0, q0+8

    float o_[8][4];
#pragma unroll
    for (int i = 0; i < 8; i++)
#pragma unroll
        for (int j = 0; j < 4; j++) o_[i][j] = 0.f;
    float m0 = -1e30f, m1 = -1e30f, l0 = 0.f, l1 = 0.f;

    const int nkt = qt + 1;
    for (int kt = 0; kt < nkt; kt++) {
        const uint32_t stg = ST0 + (kt & 1) * 32768;
        if (kt + 1 < nkt) {
            PREFETCH_KV(kt + 1, ST0 + ((kt + 1) & 1) * 32768);
            cp_commit();
            cp_wait1();
        } else {
            cp_wait0();
        }
        __syncthreads();

        // ---- S = Q K^T (split-3) ----
        float sa[8][4];
#pragma unroll
        for (int i = 0; i < 8; i++)
#pragma unroll
            for (int j = 0; j < 4; j++) sa[i][j] = 0.f;
#pragma unroll
        for (int kk = 0; kk < 4; kk++) {
            uint32_t aaddr = QH + row_a * 128 + ((kk * 32 + colg_a) ^ ((row_a & 7) << 4));
            uint32_t qh[4], ql[4];
            ldmatrix_x4(qh, aaddr);
            ldmatrix_x4(ql, aaddr + 8192);
#pragma unroll
            for (int ntp = 0; ntp < 4; ntp++) {
                int rb = ntp * 16 + row_kb;
                uint32_t baddr = stg + rb * 128 + ((kk * 32 + col_kb) ^ ((rb & 7) << 4));
                uint32_t kh[4], kl[4];
                ldmatrix_x4(kh, baddr);
                ldmatrix_x4(kl, baddr + 8192);
                mma_bf16(sa[2 * ntp],     qh, kh);
                mma_bf16(sa[2 * ntp + 1], qh, kh + 2);
                mma_bf16(sa[2 * ntp],     qh, kl);
                mma_bf16(sa[2 * ntp + 1], qh, kl + 2);
                mma_bf16(sa[2 * ntp],     ql, kh);
                mma_bf16(sa[2 * ntp + 1], ql, kh + 2);
            }
        }

        // ---- online softmax ----
        const bool diag = (kt == qt);
        float rm0 = -1e30f, rm1 = -1e30f;
#pragma unroll
        for (int nt = 0; nt < 8; nt++) {
#pragma unroll
            for (int c = 0; c < 4; c++) sa[nt][c] *= 0.125f;
            if (diag) {
                int kc = kt * 64 + nt * 8 + ec;
                if (kc     > q0)     sa[nt][0] = -1e30f;
                if (kc + 1 > q0)     sa[nt][1] = -1e30f;
                if (kc     > q0 + 8) sa[nt][2] = -1e30f;
                if (kc + 1 > q0 + 8) sa[nt][3] = -1e30f;
            }
            rm0 = fmaxf(rm0, fmaxf(sa[nt][0], sa[nt][1]));
            rm1 = fmaxf(rm1, fmaxf(sa[nt][2], sa[nt][3]));
        }
        rm0 = fmaxf(rm0, __shfl_xor_sync(0xffffffffu, rm0, 1));
        rm0 = fmaxf(rm0, __shfl_xor_sync(0xffffffffu, rm0, 2));
        rm1 = fmaxf(rm1, __shfl_xor_sync(0xffffffffu, rm1, 1));
        rm1 = fmaxf(rm1, __shfl_xor_sync(0xffffffffu, rm1, 2));
        const float mn0 = fmaxf(m0, rm0), mn1 = fmaxf(m1, rm1);
        const float cr0 = __expf(m0 - mn0), cr1 = __expf(m1 - mn1);
        m0 = mn0; m1 = mn1;
        float sum0 = 0.f, sum1 = 0.f;
        const int rA = w * 16 + er;
        const uint32_t rAoff = rA * 128, rBoff = (rA + 8) * 128;
        const uint32_t xsw = (uint32_t)((rA & 7) << 4);   // same for rA and rA+8
#pragma unroll
        for (int nt = 0; nt < 8; nt++) {
            float p0 = __expf(sa[nt][0] - mn0);
            float p1 = __expf(sa[nt][1] - mn0);
            float p2 = __expf(sa[nt][2] - mn1);
            float p3 = __expf(sa[nt][3] - mn1);
            sum0 += p0 + p1; sum1 += p2 + p3;
            uint32_t hA, lA, hB, lB;
            split_pack(p0, p1, hA, lA);
            split_pack(p2, p3, hB, lB);
            uint32_t cb = (uint32_t)(nt * 16 + ec * 2) ^ xsw;
            sts32(PH + rAoff + cb, hA);
            sts32(PH + 8192 + rAoff + cb, lA);
            sts32(PH + rBoff + cb, hB);
            sts32(PH + 8192 + rBoff + cb, lB);
        }
        sum0 += __shfl_xor_sync(0xffffffffu, sum0, 1);
        sum0 += __shfl_xor_sync(0xffffffffu, sum0, 2);
        sum1 += __shfl_xor_sync(0xffffffffu, sum1, 1);
        sum1 += __shfl_xor_sync(0xffffffffu, sum1, 2);
        l0 = l0 * cr0 + sum0;
        l1 = l1 * cr1 + sum1;
#pragma unroll
        for (int nt = 0; nt < 8; nt++) {
            o_[nt][0] *= cr0; o_[nt][1] *= cr0;
            o_[nt][2] *= cr1; o_[nt][3] *= cr1;
        }
        __syncwarp();

        // ---- O += P V (split-3), V via ldmatrix.trans ----
#pragma unroll
        for (int kk2 = 0; kk2 < 4; kk2++) {
            uint32_t paddr = PH + row_a * 128 + ((kk2 * 32 + colg_a) ^ ((row_a & 7) << 4));
            uint32_t ph[4], pl[4];
            ldmatrix_x4(ph, paddr);
            ldmatrix_x4(pl, paddr + 8192);
#pragma unroll
            for (int ntp = 0; ntp < 4; ntp++) {
                int rv = kk2 * 16 + row_v;
                uint32_t vaddr = stg + 16384 + rv * 128 + ((ntp * 32 + col_v) ^ ((rv & 7) << 4));
                uint32_t vh[4], vl[4];
                ldmatrix_x4_t(vh, vaddr);
                ldmatrix_x4_t(vl, vaddr + 8192);
                mma_bf16(o_[2 * ntp],     ph, vh);
                mma_bf16(o_[2 * ntp + 1], ph, vh + 2);
                mma_bf16(o_[2 * ntp],     ph, vl);
                mma_bf16(o_[2 * ntp + 1], ph, vl + 2);
                mma_bf16(o_[2 * ntp],     pl, vh);
                mma_bf16(o_[2 * ntp + 1], pl, vh + 2);
            }
        }
        __syncthreads();
    }

    // ---- epilogue ----
    const float i0 = 1.f / l0, i1 = 1.f / l1;
    float* r0p = out + (size_t)(b * SEQ + q0) * EMB + h * HD;
    float* r1p = r0p + (size_t)8 * EMB;
#pragma unroll
    for (int nt = 0; nt < 8; nt++) {
        float2 v0 = { o_[nt][0] * i0, o_[nt][1] * i0 };
        float2 v1 = { o_[nt][2] * i1, o_[nt][3] * i1 };
        *(float2*)(r0p + nt * 8 + ec) = v0;
        *(float2*)(r1p + nt * 8 + ec) = v1;
    }
#undef PREFETCH_KV
}

// ==================== embed ====================
__global__ void __launch_bounds__(256) embed_kernel(
    const int* __restrict__ x, const float* __restrict__ we,
    const float* __restrict__ pe, float* __restrict__ h)
{
    int row = blockIdx.x;
    int s   = row % SEQ;
    int tok = x[row];
    int c = threadIdx.x * 4;
    float4 a = *(const float4*)(we + (size_t)tok * EMB + c);
    float4 b = *(const float4*)(pe + (size_t)s   * EMB + c);
    float4 o; o.x = a.x + b.x; o.y = a.y + b.y; o.z = a.z + b.z; o.w = a.w + b.w;
    *(float4*)(h + (size_t)row * EMB + c) = o;
}

// ==================== fused LayerNorm + residual ====================
__global__ void __launch_bounds__(256) ln_add_kernel(
    const float* __restrict__ x, const float* __restrict__ gam,
    const float* __restrict__ bet, float* __restrict__ h)
{
    const int row = blockIdx.x;
    const int tid = threadIdx.x;
    __shared__ float red[8];
    __shared__ float stats[2];

    const float* xr = x + (size_t)row * EMB;
    const int c = tid * 4;
    float4 v = *(const float4*)(xr + c);
    float s = v.x + v.y + v.z + v.w;
#pragma unroll
    for (int o = 16; o; o >>= 1) s += __shfl_xor_sync(0xffffffffu, s, o);
    if ((tid & 31) == 0) red[tid >> 5] = s;
    __syncthreads();
    if (tid == 0) {
        float t = 0.f;
#pragma unroll
        for (int i = 0; i < 8; i++) t += red[i];
        stats[0] = t * (1.f / EMB);
    }
    __syncthreads();
    const float mu = stats[0];

    float dx0 = v.x - mu, dx1 = v.y - mu, dx2 = v.z - mu, dx3 = v.w - mu;
    float sq = dx0 * dx0 + dx1 * dx1 + dx2 * dx2 + dx3 * dx3;
#pragma unroll
    for (int o = 16; o; o >>= 1) sq += __shfl_xor_sync(0xffffffffu, sq, o);
    if ((tid & 31) == 0) red[tid >> 5] = sq;
    __syncthreads();
    if (tid == 0) {
        float t = 0.f;
#pragma unroll
        for (int i = 0; i < 8; i++) t += red[i];
        stats[1] = rsqrtf(t * (1.f / EMB) + 1e-6f);
    }
    __syncthreads();
    const float r = stats[1];

    float4 g4 = *(const float4*)(gam + c);
    float4 b4 = *(const float4*)(bet + c);
    float4 hv = *(float4*)(h + (size_t)row * EMB + c);
    hv.x += dx0 * r * g4.x + b4.x;
    hv.y += dx1 * r * g4.y + b4.y;
    hv.z += dx2 * r * g4.z + b4.z;
    hv.w += dx3 * r * g4.w + b4.w;
    *(float4*)(h + (size_t)row * EMB + c) = hv;
}

// ==================== host launch ====================
static void* sym_addr(const void* sym) {
    void* p = nullptr;
    cudaGetSymbolAddress(&p, sym);
    return p;
}

extern "C" void kernel_launch(void* const* d_in, const int* in_sizes, int n_in,
                              void* d_out, int out_size)
{
    const int*   x   = (const int*)d_in[0];
    const float* we  = (const float*)d_in[1];
    const float* pe  = (const float*)d_in[2];
    const float* KQV = (const float*)d_in[3];
    const float* WO  = (const float*)d_in[4];
    const float* Wup = (const float*)d_in[5];
    const float* bup = (const float*)d_in[6];
    const float* Wdn = (const float*)d_in[7];
    const float* bdn = (const float*)d_in[8];
    const float* g1  = (const float*)d_in[9];
    const float* b1  = (const float*)d_in[10];
    const float* g2  = (const float*)d_in[11];
    const float* b2  = (const float*)d_in[12];
    const float* ub  = (const float*)d_in[13];
    float* out = (float*)d_out;

    float* h    = (float*)sym_addr(g_h);
    float* qkv  = (float*)sym_addr(g_qkv);
    float* attn = (float*)sym_addr(g_attn);
    float* tmp  = (float*)sym_addr(g_tmp);
    float* ff   = (float*)sym_addr(g_ff);
    __nv_bfloat16* ahi  = (__nv_bfloat16*)sym_addr(g_ahi);
    __nv_bfloat16* alo  = (__nv_bfloat16*)sym_addr(g_alo);
    __nv_bfloat16* qkvh = (__nv_bfloat16*)sym_addr(g_qkvh);
    __nv_bfloat16* qkvl = (__nv_bfloat16*)sym_addr(g_qkvl);
    __nv_bfloat16* wkqv_h = (__nv_bfloat16*)sym_addr(g_wkqv_hi);
    __nv_bfloat16* wkqv_l = (__nv_bfloat16*)sym_addr(g_wkqv_lo);
    __nv_bfloat16* wo_h   = (__nv_bfloat16*)sym_addr(g_wo_hi);
    __nv_bfloat16* wo_l   = (__nv_bfloat16*)sym_addr(g_wo_lo);
    __nv_bfloat16* wup_h  = (__nv_bfloat16*)sym_addr(g_wup_hi);
    __nv_bfloat16* wup_l  = (__nv_bfloat16*)sym_addr(g_wup_lo);
    __nv_bfloat16* wdn_h  = (__nv_bfloat16*)sym_addr(g_wdn_hi);
    __nv_bfloat16* wdn_l  = (__nv_bfloat16*)sym_addr(g_wdn_lo);
    __nv_bfloat16* we_h   = (__nv_bfloat16*)sym_addr(g_we_hi);
    __nv_bfloat16* we_l   = (__nv_bfloat16*)sym_addr(g_we_lo);

    cudaFuncSetAttribute(hgemm_kernel<false, false>,
                         cudaFuncAttributeMaxDynamicSharedMemorySize, GEMM_SMEM);
    cudaFuncSetAttribute(hgemm_kernel<true, true>,
                         cudaFuncAttributeMaxDynamicSharedMemorySize, GEMM_SMEM);
    cudaFuncSetAttribute(hgemm_kernel<true, false>,
                         cudaFuncAttributeMaxDynamicSharedMemorySize, GEMM_SMEM);
    cudaFuncSetAttribute(flash_mma_kernel,
                         cudaFuncAttributeMaxDynamicSharedMemorySize, FA_SMEM);

    // ---- weight conversion (transpose to [N][K] + hi/lo split) ----
    dim3 tb(32, 8);
    for (int l = 0; l < NL; l++) {
        cvt_t_kernel<<<dim3(3 * EMB / 32, EMB / 32), tb>>>(
            KQV + (size_t)l * EMB * 3 * EMB,
            wkqv_h + (size_t)l * 3 * EMB * EMB, wkqv_l + (size_t)l * 3 * EMB * EMB,
            EMB, 3 * EMB);
        cvt_t_kernel<<<dim3(EMB / 32, EMB / 32), tb>>>(
            WO + (size_t)l * EMB * EMB,
            wo_h + (size_t)l * EMB * EMB, wo_l + (size_t)l * EMB * EMB,
            EMB, EMB);
        cvt_t_kernel<<<dim3(FF / 32, EMB / 32), tb>>>(
            Wup + (size_t)l * EMB * FF,
            wup_h + (size_t)l * (size_t)EMB * FF, wup_l + (size_t)l * (size_t)EMB * FF,
            EMB, FF);
        cvt_t_kernel<<<dim3(EMB / 32, FF / 32), tb>>>(
            Wdn + (size_t)l * FF * EMB,
            wdn_h + (size_t)l * (size_t)FF * EMB, wdn_l + (size_t)l * (size_t)FF * EMB,
            FF, EMB);
    }
    cvt_kernel<<<(unsigned)((size_t)VOC * EMB / 4 / 256), 256>>>(
        we, we_h, we_l, (size_t)VOC * EMB / 4);

    embed_kernel<<<BS, 256>>>(x, we, pe, h);

    const unsigned cvtE = (unsigned)((size_t)BS * EMB / 4 / 256);
    const unsigned cvtQ = (unsigned)((size_t)BS * 3 * EMB / 4 / 256);
    const unsigned cvtF = (unsigned)((size_t)BS * FF / 4 / 256);

    for (int l = 0; l < NL; l++) {
        // qkv = h @ KQV[l]
        cvt_kernel<<<cvtE, 256>>>(h, ahi, alo, (size_t)BS * EMB / 4);
        hgemm_kernel<false, false>
            <<<dim3(3 * EMB / GBN, BS / GBM), 256, GEMM_SMEM>>>(
                ahi, alo,
                wkqv_h + (size_t)l * 3 * EMB * EMB, wkqv_l + (size_t)l * 3 * EMB * EMB,
                nullptr, qkv, BS, 3 * EMB, EMB);

        // attention (tensor-core flash)
        cvt_kernel<<<cvtQ, 256>>>(qkv, qkvh, qkvl, (size_t)BS * 3 * EMB / 4);
        flash_mma_kernel<<<dim3(SEQ / 64, NH, BATCH), 128, FA_SMEM>>>(qkvh, qkvl, attn);

        // tmp = attn @ WO[l]
        cvt_kernel<<<cvtE, 256>>>(attn, ahi, alo, (size_t)BS * EMB / 4);
        hgemm_kernel<false, false>
            <<<dim3(EMB / GBN, BS / GBM), 256, GEMM_SMEM>>>(
                ahi, alo,
                wo_h + (size_t)l * EMB * EMB, wo_l + (size_t)l * EMB * EMB,
                nullptr, tmp, BS, EMB, EMB);

        ln_add_kernel<<<BS, 256>>>(tmp, g1 + l * EMB, b1 + l * EMB, h);

        // ff = relu(h @ W_up[l] + b_up[l])
        cvt_kernel<<<cvtE, 256>>>(h, ahi, alo, (size_t)BS * EMB / 4);
        hgemm_kernel<true, true>
            <<<dim3(FF / GBN, BS / GBM), 256, GEMM_SMEM>>>(
                ahi, alo,
                wup_h + (size_t)l * (size_t)EMB * FF, wup_l + (size_t)l * (size_t)EMB * FF,
                bup + (size_t)l * FF, ff, BS, FF, EMB);

        // tmp = ff @ W_down[l] + b_down[l]
        cvt_kernel<<<cvtF, 256>>>(ff, ahi, alo, (size_t)BS * FF / 4);
        hgemm_kernel<true, false>
            <<<dim3(EMB / GBN, BS / GBM), 256, GEMM_SMEM>>>(
                ahi, alo,
                wdn_h + (size_t)l * (size_t)FF * EMB, wdn_l + (size_t)l * (size_t)FF * EMB,
                bdn + (size_t)l * EMB, tmp, BS, EMB, FF);

        ln_add_kernel<<<BS, 256>>>(tmp, g2 + l * EMB, b2 + l * EMB, h);
    }

    // logits = h @ we^T + unembed_b
    cvt_kernel<<<cvtE, 256>>>(h, ahi, alo, (size_t)BS * EMB / 4);
    hgemm_kernel<true, false>
        <<<dim3(VOC / GBN, BS / GBM), 256, GEMM_SMEM>>>(
            ahi, alo, we_h, we_l, ub, out, BS, VOC, EMB);
}